// round 14
// baseline (speedup 1.0000x reference)
#include <cuda_runtime.h>
#include <math.h>

#define BATCH 128
#define TSEQ  1024
#define DIN   128
#define HID   256
#define FOURH 1024
#define DOUT  1000
#define NCTA  128
#define HB    (HID * BATCH)

// Scratch (device globals: allocation-free)
__device__ float d_xT[(size_t)TSEQ * DIN * BATCH];     // [t][k][b]  64 MB
__device__ float d_h1[2 * HB];                          // ping-pong [parity][j][b]
__device__ float d_h2[2 * HB];
__device__ int   g_cnt;

typedef unsigned long long ull;

__device__ __forceinline__ ull pack2(float lo, float hi) {
    ull r; asm("mov.b64 %0, {%1, %2};" : "=l"(r) : "f"(lo), "f"(hi)); return r;
}
__device__ __forceinline__ ull bcast2(float v) {
    ull r; asm("mov.b64 %0, {%1, %1};" : "=l"(r) : "f"(v)); return r;
}
__device__ __forceinline__ void upk(ull v, float& lo, float& hi) {
    asm("mov.b64 {%0, %1}, %2;" : "=f"(lo), "=f"(hi) : "l"(v));
}
__device__ __forceinline__ void ffma2(ull& d, ull a, ull b) {
    asm("fma.rn.f32x2 %0, %1, %2, %0;" : "+l"(d) : "l"(a), "l"(b));
}
__device__ __forceinline__ float sigmoidf(float z) {
    return __fdividef(1.0f, 1.0f + __expf(-z));
}

// ---------------------------------------------------------------------------
// Kernel 1: transpose x [B][T][D] -> d_xT [T][D][B]; zero state + counter.
// ---------------------------------------------------------------------------
__global__ void transpose_x_kernel(const float* __restrict__ x) {
    __shared__ float tile[32][129];
    const int t  = blockIdx.x;
    const int b0 = blockIdx.y * 32;
    if (blockIdx.y == 0) {
        int i = blockIdx.x * 256 + threadIdx.x;
        if (i < 2 * HB) { d_h1[i] = 0.0f; d_h2[i] = 0.0f; }
        if (blockIdx.x == 0 && threadIdx.x == 0) g_cnt = 0;
    }
    for (int idx = threadIdx.x; idx < 32 * 128; idx += 256) {
        int r = idx >> 7, k = idx & 127;
        tile[r][k] = x[(size_t)(b0 + r) * (TSEQ * DIN) + (size_t)t * DIN + k];
    }
    __syncthreads();
    for (int idx = threadIdx.x; idx < 32 * 128; idx += 256) {
        int k = idx >> 5, bb = idx & 31;
        d_xT[((size_t)t * DIN + k) * BATCH + b0 + bb] = tile[bb][k];
    }
}

// ---------------------------------------------------------------------------
// x-part: 16 k of x@W1 for batches {lane, lane+32, lane+64, lane+96}.
// Runs in the barrier shadow (role-A warps only); xacc overwritten.
// ---------------------------------------------------------------------------
__device__ __forceinline__ void compute_x(
    const float* __restrict__ xp, const ull (* __restrict__ sW1)[4],
    int kx, ull (&xacc)[4][4])
{
#pragma unroll
    for (int a = 0; a < 4; ++a)
#pragma unroll
        for (int p = 0; p < 4; ++p) xacc[a][p] = 0;
#pragma unroll 4
    for (int j = 0; j < 16; ++j) {
        float x0 = __ldcg(xp + j * BATCH);
        float x1 = __ldcg(xp + j * BATCH + 32);
        float x2 = __ldcg(xp + j * BATCH + 64);
        float x3 = __ldcg(xp + j * BATCH + 96);
        const int k = kx + j;
        ulonglong2 wa = *(const ulonglong2*)&sW1[k][0];
        ulonglong2 wb = *(const ulonglong2*)&sW1[k][2];
        ull v;
        v = bcast2(x0);
        ffma2(xacc[0][0], wa.x, v); ffma2(xacc[0][1], wa.y, v);
        ffma2(xacc[0][2], wb.x, v); ffma2(xacc[0][3], wb.y, v);
        v = bcast2(x1);
        ffma2(xacc[1][0], wa.x, v); ffma2(xacc[1][1], wa.y, v);
        ffma2(xacc[1][2], wb.x, v); ffma2(xacc[1][3], wb.y, v);
        v = bcast2(x2);
        ffma2(xacc[2][0], wa.x, v); ffma2(xacc[2][1], wa.y, v);
        ffma2(xacc[2][2], wb.x, v); ffma2(xacc[2][3], wb.y, v);
        v = bcast2(x3);
        ffma2(xacc[3][0], wa.x, v); ffma2(xacc[3][1], wa.y, v);
        ffma2(xacc[3][2], wb.x, v); ffma2(xacc[3][3], wb.y, v);
    }
}

// ---------------------------------------------------------------------------
// Kernel 2: persistent 2-layer LSTM + fused dense/softmax.
// 128 CTAs x 512 threads (16 warps). CTA owns units {2*cta, 2*cta+1}.
// Warp w = tid>>5: slice s = w>>1 (32 hidden k), role = w&1.
//   Role A (0): stream a1 = U1.h1 (+x@W1 via shadow), 4 batches/thread.
//   Role B (1): stream a2 = W2.h1 + U2.h2 merged,      4 batches/thread.
// Each weight row is loaded by exactly ONE warp (halves weight-LDS vs R11)
// while keeping 16 warps (R12's occupancy collapse avoided).
// Epilogue: thread (eb=tid&127, eu, elay=tid>>8) owns its c-state.
// Grid barrier every iteration; one warp polls; sync releases the CTA.
// ---------------------------------------------------------------------------
__global__ void __launch_bounds__(512, 1)
lstm_persistent(const float* __restrict__ W1, const float* __restrict__ U1,
                const float* __restrict__ b1, const float* __restrict__ W2,
                const float* __restrict__ U2, const float* __restrict__ b2,
                const float* __restrict__ Wd, const float* __restrict__ bd,
                float* __restrict__ out) {
    extern __shared__ __align__(16) char dyn[];
    ull (*sU1)[4] = (ull (*)[4])dyn;            // 256 rows
    ull (*sW2)[4] = sU1 + 256;                  // 256 rows
    ull (*sU2)[4] = sW2 + 256;                  // 256 rows
    ull (*sW1)[4] = sU2 + 256;                  // 128 rows
    ulonglong2* red = (ulonglong2*)(sW1 + 128); // [2 streams][2 pairs][8 s][128 slots]
#define RED2(st, pp, ss, bbx) red[((((st) << 1) + (pp)) << 10) + ((ss) << 7) + (bbx)]

    const int tid  = threadIdx.x;
    const int lane = tid & 31;
    const int w    = tid >> 5;         // warp 0..15
    const int s    = w >> 1;           // k-slice 0..7
    const int role = w & 1;            // 0 = layer-1 stream, 1 = layer-2 stream
    const int u0   = 2 * blockIdx.x;

    // Pack weights: column pairs -> 64-bit words.
    if (tid < 256) {
        int k = tid;
#pragma unroll
        for (int p = 0; p < 4; ++p) {
            int cA = 2 * p, cB = 2 * p + 1;
            int gcA = (cA & 3) * HID + u0 + (cA >> 2);
            int gcB = (cB & 3) * HID + u0 + (cB >> 2);
            sU1[k][p] = pack2(U1[k * FOURH + gcA], U1[k * FOURH + gcB]);
            sW2[k][p] = pack2(W2[k * FOURH + gcA], W2[k * FOURH + gcB]);
            sU2[k][p] = pack2(U2[k * FOURH + gcA], U2[k * FOURH + gcB]);
            if (k < 128)
                sW1[k][p] = pack2(W1[k * FOURH + gcA], W1[k * FOURH + gcB]);
        }
    }

    // Epilogue identity + biases + owned cell state
    const int eb   = tid & 127;
    const int eu   = (tid >> 7) & 1;
    const int elay = tid >> 8;
    float EB[4];
#pragma unroll
    for (int g = 0; g < 4; ++g) {
        int gc = g * HID + u0 + eu;
        EB[g] = elay ? b2[gc] : b1[gc];
    }
    float ec = 0.0f;
    __syncthreads();

    const int kh = 32 * s;   // hidden k base
    const int kx = 16 * s;   // x k base

    ull xacc[4][4];
    if (role == 0)
        compute_x(d_xT + kx * BATCH + lane, sW1, kx, xacc);

    for (int iter = 0; iter <= TSEQ; ++iter) {
        const int rp = iter & 1, wp = rp ^ 1;
        const float* __restrict__ hp1 = d_h1 + rp * HB + kh * BATCH + lane;
        const float* __restrict__ hp2 = d_h2 + rp * HB + kh * BATCH + lane;

        if (role == 0) {
            // ===== Role A: a1 = U1.h1 + xacc =====
            ull a1[4][4];
#pragma unroll
            for (int a = 0; a < 4; ++a)
#pragma unroll
                for (int p = 0; p < 4; ++p) a1[a][p] = xacc[a][p];

            float Ha[16], Hb[16];
#pragma unroll
            for (int j = 0; j < 4; ++j)
#pragma unroll
                for (int a = 0; a < 4; ++a)
                    Ha[j * 4 + a] = __ldcg(hp1 + j * BATCH + 32 * a);
#pragma unroll
            for (int blk = 0; blk < 8; ++blk) {
                float* cur = (blk & 1) ? Hb : Ha;
                float* nxt = (blk & 1) ? Ha : Hb;
                if (blk < 7) {
                    const int kn = (blk + 1) * 4;
#pragma unroll
                    for (int j = 0; j < 4; ++j)
#pragma unroll
                        for (int a = 0; a < 4; ++a)
                            nxt[j * 4 + a] = __ldcg(hp1 + (kn + j) * BATCH + 32 * a);
                }
#pragma unroll
                for (int j = 0; j < 4; ++j) {
                    const int k = kh + blk * 4 + j;
                    ulonglong2 wa = *(const ulonglong2*)&sU1[k][0];
                    ulonglong2 wb = *(const ulonglong2*)&sU1[k][2];
#pragma unroll
                    for (int a = 0; a < 4; ++a) {
                        ull v = bcast2(cur[j * 4 + a]);
                        ffma2(a1[a][0], wa.x, v); ffma2(a1[a][1], wa.y, v);
                        ffma2(a1[a][2], wb.x, v); ffma2(a1[a][3], wb.y, v);
                    }
                }
            }
#pragma unroll
            for (int a = 0; a < 4; ++a) {
                const int bx = lane + 32 * a;
                RED2(0, 0, s, bx) = make_ulonglong2(a1[a][0], a1[a][1]);
                RED2(0, 1, s, bx) = make_ulonglong2(a1[a][2], a1[a][3]);
            }
        } else {
            // ===== Role B: a2 = W2.h1 + U2.h2 =====
            ull a2[4][4] = {{0,0,0,0},{0,0,0,0},{0,0,0,0},{0,0,0,0}};
            float H1a[16], H1b[16], H2a[16], H2b[16];
#pragma unroll
            for (int j = 0; j < 4; ++j)
#pragma unroll
                for (int a = 0; a < 4; ++a) {
                    H1a[j * 4 + a] = __ldcg(hp1 + j * BATCH + 32 * a);
                    H2a[j * 4 + a] = __ldcg(hp2 + j * BATCH + 32 * a);
                }
#pragma unroll
            for (int blk = 0; blk < 8; ++blk) {
                float* c1h = (blk & 1) ? H1b : H1a;
                float* c2h = (blk & 1) ? H2b : H2a;
                float* n1h = (blk & 1) ? H1a : H1b;
                float* n2h = (blk & 1) ? H2a : H2b;
                if (blk < 7) {
                    const int kn = (blk + 1) * 4;
#pragma unroll
                    for (int j = 0; j < 4; ++j)
#pragma unroll
                        for (int a = 0; a < 4; ++a) {
                            n1h[j * 4 + a] = __ldcg(hp1 + (kn + j) * BATCH + 32 * a);
                            n2h[j * 4 + a] = __ldcg(hp2 + (kn + j) * BATCH + 32 * a);
                        }
                }
#pragma unroll
                for (int j = 0; j < 4; ++j) {
                    const int k = kh + blk * 4 + j;
                    ulonglong2 wa = *(const ulonglong2*)&sW2[k][0];
                    ulonglong2 wb = *(const ulonglong2*)&sW2[k][2];
#pragma unroll
                    for (int a = 0; a < 4; ++a) {
                        ull v = bcast2(c1h[j * 4 + a]);
                        ffma2(a2[a][0], wa.x, v); ffma2(a2[a][1], wa.y, v);
                        ffma2(a2[a][2], wb.x, v); ffma2(a2[a][3], wb.y, v);
                    }
                    wa = *(const ulonglong2*)&sU2[k][0];
                    wb = *(const ulonglong2*)&sU2[k][2];
#pragma unroll
                    for (int a = 0; a < 4; ++a) {
                        ull v = bcast2(c2h[j * 4 + a]);
                        ffma2(a2[a][0], wa.x, v); ffma2(a2[a][1], wa.y, v);
                        ffma2(a2[a][2], wb.x, v); ffma2(a2[a][3], wb.y, v);
                    }
                }
            }
#pragma unroll
            for (int a = 0; a < 4; ++a) {
                const int bx = lane + 32 * a;
                RED2(1, 0, s, bx) = make_ulonglong2(a2[a][0], a2[a][1]);
                RED2(1, 1, s, bx) = make_ulonglong2(a2[a][2], a2[a][3]);
            }
        }
        __syncthreads();   // publishes visible to epilogue

        // ---- epilogue: thread (eb, eu, elay); stream = elay ----
        if ((elay == 0 && iter < TSEQ) || (elay == 1 && iter >= 1)) {
            float z0 = 0.f, z1 = 0.f, z2 = 0.f, z3 = 0.f, t0, t1;
#pragma unroll
            for (int s2 = 0; s2 < 8; ++s2) {
                ulonglong2 v = RED2(elay, eu, s2, eb);
                upk(v.x, t0, t1); z0 += t0; z1 += t1;
                upk(v.y, t0, t1); z2 += t0; z3 += t1;
            }
            float ig = sigmoidf(z0 + EB[0]);
            float fg = sigmoidf(z1 + EB[1]);
            float gv = fmaxf(z2 + EB[2], 0.f);
            float og = sigmoidf(z3 + EB[3]);
            ec = fg * ec + ig * gv;
            float* dst = elay ? &d_h2[wp * HB + (u0 + eu) * BATCH + eb]
                              : &d_h1[wp * HB + (u0 + eu) * BATCH + eb];
            __stcg(dst, og * fmaxf(ec, 0.f));
        }
        __syncthreads();   // h stores issued + RED reads complete

        // ---- grid barrier: arrive once; ONE warp polls; sync releases CTA ----
        if (tid == 0) {
            asm volatile("red.release.gpu.global.add.s32 [%0], 1;"
                         :: "l"(&g_cnt) : "memory");
        }
        // x-part for the next step in the barrier shadow (role-A warps)
        if (role == 0 && iter < TSEQ) {
            const int tn = (iter + 1 < TSEQ) ? (iter + 1) : (TSEQ - 1);
            compute_x(d_xT + (size_t)tn * (DIN * BATCH) + kx * BATCH + lane,
                      sW1, kx, xacc);
        }
        if (tid < 32) {
            const int tgt = NCTA * (iter + 1);
            int v;
            do {
                asm volatile("ld.acquire.gpu.global.s32 %0, [%1];"
                             : "=r"(v) : "l"(&g_cnt));
            } while (v < tgt);
        }
        __syncthreads();
    }

    // ---------------- Dense + softmax (CTA = one batch row) ----------------
    {
        const int brow = blockIdx.x;
        float* shh = (float*)red;          // [256] h
        float* rb  = shh + 256;            // [16] warp partials

        if (tid < 256)
            shh[tid] = __ldcg(&d_h2[HB + tid * BATCH + brow]);
        __syncthreads();

        const int o0 = tid, o1 = tid + 512;
        float acc0 = (o0 < DOUT) ? bd[o0] : -1e30f;
        float acc1 = (o1 < DOUT) ? bd[o1] : -1e30f;
#pragma unroll 8
        for (int k = 0; k < HID; ++k) {
            float h = shh[k];
            const float* wrow = Wd + (size_t)k * DOUT;
            if (o0 < DOUT) acc0 += h * wrow[o0];
            if (o1 < DOUT) acc1 += h * wrow[o1];
        }
        float lmax = fmaxf(acc0, acc1);
#pragma unroll
        for (int off = 16; off; off >>= 1)
            lmax = fmaxf(lmax, __shfl_xor_sync(0xffffffffu, lmax, off));
        if (lane == 0) rb[w] = lmax;
        __syncthreads();
        if (tid == 0) {
            float m = rb[0];
#pragma unroll
            for (int i = 1; i < 16; ++i) m = fmaxf(m, rb[i]);
            rb[0] = m;
        }
        __syncthreads();
        const float M = rb[0];
        __syncthreads();

        float e0 = (o0 < DOUT) ? __expf(acc0 - M) : 0.f;
        float e1 = (o1 < DOUT) ? __expf(acc1 - M) : 0.f;
        float lsum = e0 + e1;
#pragma unroll
        for (int off = 16; off; off >>= 1)
            lsum += __shfl_xor_sync(0xffffffffu, lsum, off);
        if (lane == 0) rb[w] = lsum;
        __syncthreads();
        if (tid == 0) {
            float sm = 0.f;
#pragma unroll
            for (int i = 0; i < 16; ++i) sm += rb[i];
            rb[0] = sm;
        }
        __syncthreads();
        const float inv = __fdividef(1.0f, rb[0]);
        if (o0 < DOUT) out[(size_t)brow * DOUT + o0] = e0 * inv;
        if (o1 < DOUT) out[(size_t)brow * DOUT + o1] = e1 * inv;
    }
}

// ---------------------------------------------------------------------------
static const int SMEM_BYTES = (256 * 3 + 128) * 4 * 8 /*weights 28,672*/ +
                              2 * 2 * 8 * 128 * 16 /*red 65,536*/;  // 94,208

extern "C" void kernel_launch(void* const* d_in, const int* in_sizes, int n_in,
                              void* d_out, int out_size) {
    const float* x  = (const float*)d_in[0];
    const float* W1 = (const float*)d_in[1];
    const float* U1 = (const float*)d_in[2];
    const float* b1 = (const float*)d_in[3];
    const float* W2 = (const float*)d_in[4];
    const float* U2 = (const float*)d_in[5];
    const float* b2 = (const float*)d_in[6];
    const float* Wd = (const float*)d_in[7];
    const float* bd = (const float*)d_in[8];
    float* out = (float*)d_out;

    cudaFuncSetAttribute(lstm_persistent,
                         cudaFuncAttributeMaxDynamicSharedMemorySize,
                         SMEM_BYTES);

    transpose_x_kernel<<<dim3(TSEQ, 4), 256>>>(x);
    lstm_persistent<<<NCTA, 512, SMEM_BYTES>>>(W1, U1, b1, W2, U2, b2,
                                               Wd, bd, out);
}

// round 15
// speedup vs baseline: 1.4142x; 1.4142x over previous
#include <cuda_runtime.h>
#include <math.h>

#define BATCH 128
#define TSEQ  1024
#define DIN   128
#define HID   256
#define FOURH 1024
#define DOUT  1000
#define NCTA  128
#define HB    (HID * BATCH)

// Scratch (device globals: allocation-free)
__device__ float d_xT[(size_t)TSEQ * DIN * BATCH];     // [t][k][b]  64 MB
__device__ float d_h1[2 * HB];                          // ping-pong [parity][j][b]
__device__ float d_h2[2 * HB];
__device__ int   g_cnt;

typedef unsigned long long ull;

__device__ __forceinline__ ull pack2(float lo, float hi) {
    ull r; asm("mov.b64 %0, {%1, %2};" : "=l"(r) : "f"(lo), "f"(hi)); return r;
}
__device__ __forceinline__ ull bcast2(float v) {
    ull r; asm("mov.b64 %0, {%1, %1};" : "=l"(r) : "f"(v)); return r;
}
__device__ __forceinline__ void upk(ull v, float& lo, float& hi) {
    asm("mov.b64 {%0, %1}, %2;" : "=f"(lo), "=f"(hi) : "l"(v));
}
__device__ __forceinline__ void ffma2(ull& d, ull a, ull b) {
    asm("fma.rn.f32x2 %0, %1, %2, %0;" : "+l"(d) : "l"(a), "l"(b));
}
__device__ __forceinline__ void fadd2(ull& d, ull a) {
    asm("add.rn.f32x2 %0, %0, %1;" : "+l"(d) : "l"(a));
}
__device__ __forceinline__ float sigmoidf(float z) {
    return __fdividef(1.0f, 1.0f + __expf(-z));
}

// ---------------------------------------------------------------------------
// Kernel 1: transpose x [B][T][D] -> d_xT [T][D][B]; zero state + counter.
// ---------------------------------------------------------------------------
__global__ void transpose_x_kernel(const float* __restrict__ x) {
    __shared__ float tile[32][129];
    const int t  = blockIdx.x;
    const int b0 = blockIdx.y * 32;
    if (blockIdx.y == 0) {
        int i = blockIdx.x * 256 + threadIdx.x;
        if (i < 2 * HB) { d_h1[i] = 0.0f; d_h2[i] = 0.0f; }
        if (blockIdx.x == 0 && threadIdx.x == 0) g_cnt = 0;
    }
    for (int idx = threadIdx.x; idx < 32 * 128; idx += 256) {
        int r = idx >> 7, k = idx & 127;
        tile[r][k] = x[(size_t)(b0 + r) * (TSEQ * DIN) + (size_t)t * DIN + k];
    }
    __syncthreads();
    for (int idx = threadIdx.x; idx < 32 * 128; idx += 256) {
        int k = idx >> 5, bb = idx & 31;
        d_xT[((size_t)t * DIN + k) * BATCH + b0 + bb] = tile[bb][k];
    }
}

// ---------------------------------------------------------------------------
// x-part: 16 k of x@W1 for this thread's slice -> xacc (overwritten).
// ---------------------------------------------------------------------------
__device__ __forceinline__ void compute_x(
    const float* __restrict__ xp, const ull (* __restrict__ sW1)[4],
    int kx, ull (&xacc)[2][4])
{
#pragma unroll
    for (int a = 0; a < 2; ++a)
#pragma unroll
        for (int p = 0; p < 4; ++p) xacc[a][p] = 0;
    float X[32];
#pragma unroll
    for (int j = 0; j < 16; ++j) {
        X[2 * j]     = __ldcg(xp + j * BATCH);
        X[2 * j + 1] = __ldcg(xp + j * BATCH + 64);
    }
#pragma unroll
    for (int j = 0; j < 16; ++j) {
        const int k = kx + j;
        ull xa = bcast2(X[2 * j]);
        ull xb = bcast2(X[2 * j + 1]);
        ulonglong2 wa = *(const ulonglong2*)&sW1[k][0];
        ulonglong2 wb = *(const ulonglong2*)&sW1[k][2];
        ffma2(xacc[0][0], wa.x, xa); ffma2(xacc[0][1], wa.y, xa);
        ffma2(xacc[0][2], wb.x, xa); ffma2(xacc[0][3], wb.y, xa);
        ffma2(xacc[1][0], wa.x, xb); ffma2(xacc[1][1], wa.y, xb);
        ffma2(xacc[1][2], wb.x, xb); ffma2(xacc[1][3], wb.y, xb);
    }
}

// ---------------------------------------------------------------------------
// Kernel 2: persistent 2-layer LSTM + fused dense/softmax.
// 128 CTAs x 512 threads; CTA owns units {2*cta, 2*cta+1} of both layers.
// Dot: thread (bb=tid&63, s=tid>>6) covers batches {bb,bb+64}, hidden k
// [32s,32s+32), x k [16s,16s+16). Layer-2 accumulates W2.h1 + U2.h2 into a
// SINGLE accumulator in-loop. x@W1(t+1) computed in the barrier shadow.
// Grid barrier every iteration; ONE warp polls the counter, CTA released
// by __syncthreads (all-warp polling measured as a 1.5x regression - R10;
// stream-split role warps measured as a 1.4x regression - R13).
// Epilogue accumulates z in packed f32x2 (fadd2) - halves its chain length.
// ---------------------------------------------------------------------------
__global__ void __launch_bounds__(512, 1)
lstm_persistent(const float* __restrict__ W1, const float* __restrict__ U1,
                const float* __restrict__ b1, const float* __restrict__ W2,
                const float* __restrict__ U2, const float* __restrict__ b2,
                const float* __restrict__ Wd, const float* __restrict__ bd,
                float* __restrict__ out) {
    extern __shared__ __align__(16) char dyn[];
    ull (*sU1)[4] = (ull (*)[4])dyn;            // 256 rows
    ull (*sW2)[4] = sU1 + 256;                  // 256 rows
    ull (*sU2)[4] = sW2 + 256;                  // 256 rows
    ull (*sW1)[4] = sU2 + 256;                  // 128 rows
    ulonglong2* red = (ulonglong2*)(sW1 + 128); // [2 streams][2 pairs][8 s][128 slots]
#define RED2(st, pp, ss, bbx) red[((((st) << 1) + (pp)) << 10) + ((ss) << 7) + (bbx)]

    const int tid = threadIdx.x;
    const int bb  = tid & 63;
    const int s   = tid >> 6;          // k-slice 0..7
    const int u0  = 2 * blockIdx.x;

    // Pack weights: column pairs -> 64-bit words.
    if (tid < 256) {
        int k = tid;
#pragma unroll
        for (int p = 0; p < 4; ++p) {
            int cA = 2 * p, cB = 2 * p + 1;
            int gcA = (cA & 3) * HID + u0 + (cA >> 2);
            int gcB = (cB & 3) * HID + u0 + (cB >> 2);
            sU1[k][p] = pack2(U1[k * FOURH + gcA], U1[k * FOURH + gcB]);
            sW2[k][p] = pack2(W2[k * FOURH + gcA], W2[k * FOURH + gcB]);
            sU2[k][p] = pack2(U2[k * FOURH + gcA], U2[k * FOURH + gcB]);
            if (k < 128)
                sW1[k][p] = pack2(W1[k * FOURH + gcA], W1[k * FOURH + gcB]);
        }
    }

    // Epilogue identity + biases + owned cell state
    const int eb   = tid & 127;
    const int eu   = (tid >> 7) & 1;
    const int elay = tid >> 8;
    float EB[4];
#pragma unroll
    for (int g = 0; g < 4; ++g) {
        int gc = g * HID + u0 + eu;
        EB[g] = elay ? b2[gc] : b1[gc];
    }
    float ec = 0.0f;
    __syncthreads();

    const int kh = 32 * s;   // hidden k base
    const int kx = 16 * s;   // x k base

    ull xacc[2][4];
    compute_x(d_xT + (size_t)0 + kx * BATCH + bb, sW1, kx, xacc);

    for (int iter = 0; iter <= TSEQ; ++iter) {
        const int rp = iter & 1, wp = rp ^ 1;
        const float* __restrict__ hp1 = d_h1 + rp * HB + kh * BATCH + bb;
        const float* __restrict__ hp2 = d_h2 + rp * HB + kh * BATCH + bb;

        ull a1[2][4], a2[2][4] = {{0,0,0,0},{0,0,0,0}};
#pragma unroll
        for (int a = 0; a < 2; ++a)
#pragma unroll
            for (int p = 0; p < 4; ++p) a1[a][p] = xacc[a][p];

        // ---- hidden part (32 k), 4-k double-buffered pipeline ----
        {
            float Ha[16], Hbuf[16];
#pragma unroll
            for (int j = 0; j < 4; ++j) {
                Ha[4 * j + 0] = __ldcg(hp1 + j * BATCH);
                Ha[4 * j + 1] = __ldcg(hp1 + j * BATCH + 64);
                Ha[4 * j + 2] = __ldcg(hp2 + j * BATCH);
                Ha[4 * j + 3] = __ldcg(hp2 + j * BATCH + 64);
            }
#pragma unroll
            for (int blk = 0; blk < 8; ++blk) {
                float* cur = (blk & 1) ? Hbuf : Ha;
                float* nxt = (blk & 1) ? Ha : Hbuf;
                if (blk < 7) {
                    const int kn = (blk + 1) * 4;
#pragma unroll
                    for (int j = 0; j < 4; ++j) {
                        nxt[4 * j + 0] = __ldcg(hp1 + (kn + j) * BATCH);
                        nxt[4 * j + 1] = __ldcg(hp1 + (kn + j) * BATCH + 64);
                        nxt[4 * j + 2] = __ldcg(hp2 + (kn + j) * BATCH);
                        nxt[4 * j + 3] = __ldcg(hp2 + (kn + j) * BATCH + 64);
                    }
                }
#pragma unroll
                for (int j = 0; j < 4; ++j) {
                    const int k = kh + blk * 4 + j;
                    ull h1a = bcast2(cur[4 * j + 0]);
                    ull h1b = bcast2(cur[4 * j + 1]);
                    ull h2a = bcast2(cur[4 * j + 2]);
                    ull h2b = bcast2(cur[4 * j + 3]);
                    ulonglong2 wa = *(const ulonglong2*)&sU1[k][0];
                    ulonglong2 wb = *(const ulonglong2*)&sU1[k][2];
                    ffma2(a1[0][0], wa.x, h1a); ffma2(a1[0][1], wa.y, h1a);
                    ffma2(a1[0][2], wb.x, h1a); ffma2(a1[0][3], wb.y, h1a);
                    ffma2(a1[1][0], wa.x, h1b); ffma2(a1[1][1], wa.y, h1b);
                    ffma2(a1[1][2], wb.x, h1b); ffma2(a1[1][3], wb.y, h1b);
                    wa = *(const ulonglong2*)&sW2[k][0];
                    wb = *(const ulonglong2*)&sW2[k][2];
                    ffma2(a2[0][0], wa.x, h1a); ffma2(a2[0][1], wa.y, h1a);
                    ffma2(a2[0][2], wb.x, h1a); ffma2(a2[0][3], wb.y, h1a);
                    ffma2(a2[1][0], wa.x, h1b); ffma2(a2[1][1], wa.y, h1b);
                    ffma2(a2[1][2], wb.x, h1b); ffma2(a2[1][3], wb.y, h1b);
                    wa = *(const ulonglong2*)&sU2[k][0];
                    wb = *(const ulonglong2*)&sU2[k][2];
                    ffma2(a2[0][0], wa.x, h2a); ffma2(a2[0][1], wa.y, h2a);
                    ffma2(a2[0][2], wb.x, h2a); ffma2(a2[0][3], wb.y, h2a);
                    ffma2(a2[1][0], wa.x, h2b); ffma2(a2[1][1], wa.y, h2b);
                    ffma2(a2[1][2], wb.x, h2b); ffma2(a2[1][3], wb.y, h2b);
                }
            }
        }

        // ---- publish slice partials (16B stores) ----
#pragma unroll
        for (int a = 0; a < 2; ++a) {
            const int bx = bb + 64 * a;
            RED2(0, 0, s, bx) = make_ulonglong2(a1[a][0], a1[a][1]);
            RED2(0, 1, s, bx) = make_ulonglong2(a1[a][2], a1[a][3]);
            RED2(1, 0, s, bx) = make_ulonglong2(a2[a][0], a2[a][1]);
            RED2(1, 1, s, bx) = make_ulonglong2(a2[a][2], a2[a][3]);
        }
        __syncthreads();   // publishes visible to epilogue

        // ---- epilogue: thread (eb, eu, elay); stream = elay; packed adds ----
        if ((elay == 0 && iter < TSEQ) || (elay == 1 && iter >= 1)) {
            ull zA = 0, zB = 0;      // packed (z0,z1), (z2,z3)
#pragma unroll
            for (int s2 = 0; s2 < 8; ++s2) {
                ulonglong2 v = RED2(elay, eu, s2, eb);
                fadd2(zA, v.x);
                fadd2(zB, v.y);
            }
            float z0, z1, z2, z3;
            upk(zA, z0, z1);
            upk(zB, z2, z3);
            float ig = sigmoidf(z0 + EB[0]);
            float fg = sigmoidf(z1 + EB[1]);
            float gv = fmaxf(z2 + EB[2], 0.f);
            float og = sigmoidf(z3 + EB[3]);
            ec = fg * ec + ig * gv;
            float* dst = elay ? &d_h2[wp * HB + (u0 + eu) * BATCH + eb]
                              : &d_h1[wp * HB + (u0 + eu) * BATCH + eb];
            __stcg(dst, og * fmaxf(ec, 0.f));
        }
        __syncthreads();   // h stores issued + RED reads complete

        // ---- grid barrier: arrive once; ONE warp polls; sync releases CTA ----
        if (tid == 0) {
            asm volatile("red.release.gpu.global.add.s32 [%0], 1;"
                         :: "l"(&g_cnt) : "memory");
        }
        // x-part for the next step in the barrier shadow
        if (iter < TSEQ) {
            const int tn = (iter + 1 < TSEQ) ? (iter + 1) : (TSEQ - 1);
            compute_x(d_xT + (size_t)tn * (DIN * BATCH) + kx * BATCH + bb,
                      sW1, kx, xacc);
        }
        if (tid < 32) {
            const int tgt = NCTA * (iter + 1);
            int v;
            do {
                asm volatile("ld.acquire.gpu.global.s32 %0, [%1];"
                             : "=r"(v) : "l"(&g_cnt));
            } while (v < tgt);
        }
        __syncthreads();
    }

    // ---------------- Dense + softmax (CTA = one batch row) ----------------
    {
        const int brow = blockIdx.x;
        float* shh = (float*)red;          // [256] h
        float* rb  = shh + 256;            // [16] warp partials

        if (tid < 256)
            shh[tid] = __ldcg(&d_h2[HB + tid * BATCH + brow]);
        __syncthreads();

        const int o0 = tid, o1 = tid + 512;
        float acc0 = (o0 < DOUT) ? bd[o0] : -1e30f;
        float acc1 = (o1 < DOUT) ? bd[o1] : -1e30f;
#pragma unroll 8
        for (int k = 0; k < HID; ++k) {
            float h = shh[k];
            const float* wrow = Wd + (size_t)k * DOUT;
            if (o0 < DOUT) acc0 += h * wrow[o0];
            if (o1 < DOUT) acc1 += h * wrow[o1];
        }
        float lmax = fmaxf(acc0, acc1);
#pragma unroll
        for (int off = 16; off; off >>= 1)
            lmax = fmaxf(lmax, __shfl_xor_sync(0xffffffffu, lmax, off));
        if ((tid & 31) == 0) rb[tid >> 5] = lmax;
        __syncthreads();
        if (tid == 0) {
            float m = rb[0];
#pragma unroll
            for (int i = 1; i < 16; ++i) m = fmaxf(m, rb[i]);
            rb[0] = m;
        }
        __syncthreads();
        const float M = rb[0];
        __syncthreads();

        float e0 = (o0 < DOUT) ? __expf(acc0 - M) : 0.f;
        float e1 = (o1 < DOUT) ? __expf(acc1 - M) : 0.f;
        float lsum = e0 + e1;
#pragma unroll
        for (int off = 16; off; off >>= 1)
            lsum += __shfl_xor_sync(0xffffffffu, lsum, off);
        if ((tid & 31) == 0) rb[tid >> 5] = lsum;
        __syncthreads();
        if (tid == 0) {
            float sm = 0.f;
#pragma unroll
            for (int i = 0; i < 16; ++i) sm += rb[i];
            rb[0] = sm;
        }
        __syncthreads();
        const float inv = __fdividef(1.0f, rb[0]);
        if (o0 < DOUT) out[(size_t)brow * DOUT + o0] = e0 * inv;
        if (o1 < DOUT) out[(size_t)brow * DOUT + o1] = e1 * inv;
    }
}

// ---------------------------------------------------------------------------
static const int SMEM_BYTES = (256 * 3 + 128) * 4 * 8 /*weights 28,672*/ +
                              2 * 2 * 8 * 128 * 16 /*red 65,536*/;  // 94,208

extern "C" void kernel_launch(void* const* d_in, const int* in_sizes, int n_in,
                              void* d_out, int out_size) {
    const float* x  = (const float*)d_in[0];
    const float* W1 = (const float*)d_in[1];
    const float* U1 = (const float*)d_in[2];
    const float* b1 = (const float*)d_in[3];
    const float* W2 = (const float*)d_in[4];
    const float* U2 = (const float*)d_in[5];
    const float* b2 = (const float*)d_in[6];
    const float* Wd = (const float*)d_in[7];
    const float* bd = (const float*)d_in[8];
    float* out = (float*)d_out;

    cudaFuncSetAttribute(lstm_persistent,
                         cudaFuncAttributeMaxDynamicSharedMemorySize,
                         SMEM_BYTES);

    transpose_x_kernel<<<dim3(TSEQ, 4), 256>>>(x);
    lstm_persistent<<<NCTA, 512, SMEM_BYTES>>>(W1, U1, b1, W2, U2, b2,
                                               Wd, bd, out);
}